// round 15
// baseline (speedup 1.0000x reference)
#include <cuda_runtime.h>
#include <stdint.h>

// preds: [32, 3, 640, 640] fp32
#define B_     32
#define H_     640
#define W_     640
#define HW_    (H_ * W_)          // 409600 floats per channel
#define TOPK_  1000
#define NB2    2048               // sort buckets
#define CAP    4096
#define TG     2.6f               // static fast-path threshold (p~0.0047 -> ~1900/img)
#define BX     100                // pass blocks per image (4096 floats each)
#define TPB    256
#define STAGE  1024

typedef unsigned long long ull;

// Device scratch (zero at load; kernel restores counters each execution)
__device__ ull g_cand[B_ * CAP];
__device__ ull g_sorted[B_ * CAP];   // only used when M > 2048 (fallback-ish)
__device__ int g_count[B_];
__device__ int g_done[B_];

// Order-preserving bijection float -> uint (monotone increasing)
__device__ __forceinline__ unsigned int ordf(float x) {
    unsigned int u = __float_as_uint(x);
    return (u & 0x80000000u) ? ~u : (u | 0x80000000u);
}

__global__ void __launch_bounds__(TPB, 6) k_fused(const float* __restrict__ preds,
                                                  float* __restrict__ out) {
    // 32 KB aliased buffer:
    //   pass:   stage[1024] ull           -> buf[0:8K]
    //   select: kgrp[2048] ull            -> buf[0:16K]
    //           hist[2048] u32            -> buf[16K:24K]
    //           start[2048] u32           -> buf[24K:32K]
    __shared__ __align__(16) unsigned char buf[32768];
    __shared__ unsigned int part[TPB];        // 1 KB (fallback scan only)
    __shared__ unsigned int wtmp[8], wtmp2[8];
    __shared__ unsigned int sh_mn, sh_sh;
    __shared__ int sh_cnt, sh_base, sh_ovf, sh_flag, sh_T, sh_c2;

    const int b = blockIdx.y;
    const int t = threadIdx.x;
    const int lane = t & 31;
    const int wid = t >> 5;

    const float* __restrict__ chan = preds + (size_t)b * 3 * HW_;

    // ======================= PASS PHASE (champion structure) =======================
    {
        ull* stage = (ull*)buf;
        if (t == 0) { sh_cnt = 0; sh_ovf = 0; }
        __syncthreads();

        const float4* __restrict__ sc = (const float4*)chan;
        const int tid = blockIdx.x * TPB + t;   // 0..25599

        float4 v[4];
#pragma unroll
        for (int j = 0; j < 4; j++) v[j] = sc[tid + j * 25600];

        float mx = v[0].x;
#pragma unroll
        for (int j = 0; j < 4; j++) {
            mx = fmaxf(mx, fmaxf(fmaxf(v[j].x, v[j].y), fmaxf(v[j].z, v[j].w)));
        }

        unsigned int m = 0;
        if (mx >= TG) {
#pragma unroll
            for (int j = 0; j < 4; j++) {
                m |= (v[j].x >= TG) ? (1u << (4 * j + 0)) : 0u;
                m |= (v[j].y >= TG) ? (1u << (4 * j + 1)) : 0u;
                m |= (v[j].z >= TG) ? (1u << (4 * j + 2)) : 0u;
                m |= (v[j].w >= TG) ? (1u << (4 * j + 3)) : 0u;
            }
        }

        const int nh = __popc(m);
        if (__ballot_sync(0xFFFFFFFFu, nh) != 0) {
            int pre = nh;
#pragma unroll
            for (int off = 1; off < 32; off <<= 1) {
                int y = __shfl_up_sync(0xFFFFFFFFu, pre, off);
                if (lane >= off) pre += y;
            }
            const int tot = __shfl_sync(0xFFFFFFFFu, pre, 31);
            int wbase = 0;
            if (lane == 31) wbase = atomicAdd(&sh_cnt, tot);
            wbase = __shfl_sync(0xFFFFFFFFu, wbase, 31);

            int pos = wbase + pre - nh;
            if (nh) {
#pragma unroll
                for (int j = 0; j < 4; j++) {
                    const int i4 = tid + j * 25600;
                    const float f0 = v[j].x, f1 = v[j].y, f2 = v[j].z, f3 = v[j].w;
#pragma unroll
                    for (int k = 0; k < 4; k++) {
                        if (m & (1u << (4 * j + k))) {
                            if (pos < STAGE) {
                                const float f = (k == 0) ? f0 : (k == 1) ? f1 : (k == 2) ? f2 : f3;
                                const unsigned int o = ordf(f);
                                const unsigned int idx = (unsigned int)(i4 * 4 + k);
                                stage[pos] = ((ull)o << 32) | (ull)(0xFFFFFFFFu - idx);
                            } else {
                                sh_ovf = 1;
                            }
                            pos++;
                        }
                    }
                }
            }
        }
        __syncthreads();

        if (t == 0) {
            int add = sh_cnt + (sh_ovf ? 1000000 : 0);   // poison on overflow
            sh_base = add ? atomicAdd(&g_count[b], add) : 0;
        }
        __syncthreads();

        const int cnt = min(sh_cnt, STAGE);
        const int base = sh_base;
        for (int i = t; i < cnt; i += TPB) {
            const int p = base + i;
            if (p < CAP) g_cand[b * CAP + p] = stage[i];
        }
    }

    // ===== DONE-COUNTER (release/acquire; last block per image selects) =====
    __syncthreads();
    if (t == 0) {
        int old;
        asm volatile("atom.acq_rel.gpu.global.add.s32 %0, [%1], 1;"
                     : "=r"(old) : "l"(&g_done[b]) : "memory");
        sh_flag = (old == BX - 1);
    }
    __syncthreads();
    if (!sh_flag) return;

    // ======================= SELECT PHASE (256 threads) =======================
    ull*          kgrp_s = (ull*)buf;                        // 16 KB
    unsigned int* hist   = (unsigned int*)(buf + 16384);     //  8 KB
    unsigned int* start  = (unsigned int*)(buf + 24576);     //  8 KB

    int M = g_count[b];

    // ============ FALLBACK (never taken for valid fast path) ============
    if (M < TOPK_ || M > CAP) {
        for (int i = t; i < NB2; i += TPB) hist[i] = 0u;
        if (t == 0) { sh_T = 0; sh_c2 = 0; }
        __syncthreads();

        const float4* sc = (const float4*)chan;
        for (int i = t; i < HW_ / 4; i += TPB) {
            const float4 w = sc[i];
            atomicAdd(&hist[ordf(w.x) >> 21], 1u);
            atomicAdd(&hist[ordf(w.y) >> 21], 1u);
            atomicAdd(&hist[ordf(w.z) >> 21], 1u);
            atomicAdd(&hist[ordf(w.w) >> 21], 1u);
        }
        __syncthreads();

        unsigned int seg = 0;
        for (int j = 7; j >= 0; j--) seg += hist[t * 8 + j];
        part[t] = seg;
        __syncthreads();
        for (int off = 1; off < TPB; off <<= 1) {
            unsigned int vv = (t + off < TPB) ? part[t + off] : 0u;
            __syncthreads();
            part[t] += vv;
            __syncthreads();
        }
        unsigned int acc = part[t] - seg;
        for (int j = 7; j >= 0; j--) {
            acc += hist[t * 8 + j];
            if (acc >= (unsigned)TOPK_) { atomicMax(&sh_T, t * 8 + j); break; }
        }
        __syncthreads();
        const unsigned int T = (unsigned int)sh_T;

        for (int i = t; i < HW_ / 4; i += TPB) {
            const float4 w = sc[i];
            const float f[4] = {w.x, w.y, w.z, w.w};
#pragma unroll
            for (int k = 0; k < 4; k++) {
                const unsigned int o = ordf(f[k]);
                if ((o >> 21) >= T) {
                    const int p = atomicAdd(&sh_c2, 1);
                    if (p < CAP) {
                        const unsigned int idx = (unsigned int)(i * 4 + k);
                        g_cand[b * CAP + p] = ((ull)o << 32) | (ull)(0xFFFFFFFFu - idx);
                    }
                }
            }
        }
        __syncthreads();
        M = min(sh_c2, CAP);
    }
    M = min(M, CAP);

    ull* kgrp = (M <= 2048) ? kgrp_s : &g_sorted[b * CAP];
    const ull* __restrict__ cand = &g_cand[b * CAP];

    // ---- min/max of candidate high words (global read, L2-hot) ----
    unsigned int lmin = 0xFFFFFFFFu, lmax = 0u;
    for (int i = t; i < M; i += TPB) {
        const unsigned int h = (unsigned int)(cand[i] >> 32);
        lmin = min(lmin, h);
        lmax = max(lmax, h);
    }
#pragma unroll
    for (int off = 16; off > 0; off >>= 1) {
        lmin = min(lmin, __shfl_down_sync(0xFFFFFFFFu, lmin, off));
        lmax = max(lmax, __shfl_down_sync(0xFFFFFFFFu, lmax, off));
    }
    if (lane == 0) { wtmp[wid] = lmin; wtmp2[wid] = lmax; }
    for (int i = t; i < NB2; i += TPB) hist[i] = 0u;
    __syncthreads();
    if (t == 0) {
        unsigned int mn = 0xFFFFFFFFu, mx = 0u;
#pragma unroll
        for (int i = 0; i < 8; i++) { mn = min(mn, wtmp[i]); mx = max(mx, wtmp2[i]); }
        const unsigned int range = mx - mn;
        const int bits = 32 - __clz(range | 1u);
        sh_sh = (bits > 11) ? (unsigned)(bits - 11) : 0u;
        sh_mn = mn;
    }
    __syncthreads();
    const unsigned int mn = sh_mn, shf = sh_sh;

    // ---- histogram (second L2-hot sweep of cand) ----
    for (int i = t; i < M; i += TPB) {
        const unsigned int h = (unsigned int)(cand[i] >> 32);
        atomicAdd(&hist[(h - mn) >> shf], 1u);
    }
    __syncthreads();

    // ---- hierarchical suffix scan over 2048 buckets (8 per thread) ----
    unsigned int hv[8];
    unsigned int s_own = 0;
#pragma unroll
    for (int j = 0; j < 8; j++) { hv[j] = hist[8 * t + j]; s_own += hv[j]; }
    unsigned int s_incl = s_own;
#pragma unroll
    for (int off = 1; off < 32; off <<= 1) {
        unsigned int y = __shfl_down_sync(0xFFFFFFFFu, s_incl, off);
        if (lane + off < 32) s_incl += y;
    }
    if (lane == 0) wtmp[wid] = s_incl;
    __syncthreads();
    if (wid == 0 && lane < 8) {
        const unsigned int wv = wtmp[lane];
        unsigned int wincl = wv;
#pragma unroll
        for (int off = 1; off < 8; off <<= 1) {
            unsigned int y = __shfl_down_sync(0x000000FFu, wincl, off);
            if (lane + off < 8) wincl += y;
        }
        wtmp[lane] = wincl - wv;    // totals of warps ABOVE this warp
    }
    __syncthreads();
    {
        unsigned int run = wtmp[wid] + (s_incl - s_own);  // keys in buckets > 8t+7
#pragma unroll
        for (int j = 7; j >= 0; j--) {
            start[8 * t + j] = run;
            run += hv[j];
            hist[8 * t + j] = 0u;   // -> intra-bucket counters
        }
    }
    __syncthreads();

    // ---- scatter: group each bucket contiguously (unordered within) ----
    for (int i = t; i < M; i += TPB) {
        const ull key = cand[i];
        const unsigned int bk = ((unsigned int)(key >> 32) - mn) >> shf;
        const unsigned int p = start[bk] + atomicAdd(&hist[bk], 1u);
        kgrp[p] = key;
    }
    __syncthreads();
    // hist[bk] now holds bucket count c

    // ---- parallel rank-within-bucket + FUSED emit ----
    const float* ph = chan + HW_;
    const float* pw = ph + HW_;
    float* boxes  = out;                              // [B, K, 4]
    float* scores = out + (size_t)B_ * TOPK_ * 4;     // [B, K]
    float* keep   = scores + (size_t)B_ * TOPK_;      // [B, K]

    for (int p = t; p < M; p += TPB) {
        const ull key = kgrp[p];
        const unsigned int bk = ((unsigned int)(key >> 32) - mn) >> shf;
        const unsigned int st = start[bk];
        const unsigned int c  = hist[bk];
        unsigned int r = 0;
        for (unsigned int q = 0; q < c; q++) r += (kgrp[st + q] > key);
        const unsigned int grank = st + r;    // exact global rank (keys unique)
        if (grank < (unsigned)TOPK_) {
            const unsigned int o = (unsigned int)(key >> 32);
            const unsigned int u = (o & 0x80000000u) ? (o ^ 0x80000000u) : ~o;
            const float score = __uint_as_float(u);
            const unsigned int idx = 0xFFFFFFFFu - (unsigned int)(key & 0xFFFFFFFFull);

            const float h = fmaxf(ph[idx], 1e-6f) * (float)H_;
            const float w = fmaxf(pw[idx], 1e-6f) * (float)W_;
            const float cx = (float)(idx % W_);
            const float cy = (float)(idx / W_);

            float* bx = boxes + ((size_t)b * TOPK_ + grank) * 4;
            bx[0] = cx - 0.5f * w;
            bx[1] = cy - 0.5f * h;
            bx[2] = cx + 0.5f * w;
            bx[3] = cy + 0.5f * h;
            scores[b * TOPK_ + grank] = score;
            keep[b * TOPK_ + grank]   = 1.0f;
        }
    }

    // reset state for next graph replay
    if (t == 0) { g_count[b] = 0; g_done[b] = 0; }
}

// ---------------------------------------------------------------------------
extern "C" void kernel_launch(void* const* d_in, const int* in_sizes, int n_in,
                              void* d_out, int out_size) {
    const float* preds = (const float*)d_in[0];
    float* out = (float*)d_out;

    dim3 g(BX, B_);
    k_fused<<<g, TPB>>>(preds, out);
}

// round 16
// speedup vs baseline: 1.7738x; 1.7738x over previous
#include <cuda_runtime.h>
#include <stdint.h>

// preds: [32, 3, 640, 640] fp32
#define B_     32
#define H_     640
#define W_     640
#define HW_    (H_ * W_)          // 409600 floats per channel
#define TOPK_  1000
#define NB2    2048               // sort buckets
#define CAP    4096
#define TG     2.6f               // static fast-path threshold (p~0.0047 -> ~1900/img)
#define BX     100                // pass blocks per image (4096 floats each)
#define TPB    256
#define STAGE  1024
// static monotone bucket map: ord(2.6f) = 0xC0266666, 2^13 per bucket
#define MN_ORD 0xC0266666u
#define BSHIFT 13

typedef unsigned long long ull;

// Device scratch (zero at load; k_select restores everything each execution)
__device__ ull          g_cand[B_ * CAP];
__device__ ull          g_sorted[B_ * CAP];   // used only when M > 2048
__device__ unsigned int g_hist[B_ * NB2];
__device__ int          g_count[B_];

// Order-preserving bijection float -> uint (monotone increasing)
__device__ __forceinline__ unsigned int ordf(float x) {
    unsigned int u = __float_as_uint(x);
    return (u & 0x80000000u) ? ~u : (u | 0x80000000u);
}

__device__ __forceinline__ unsigned int sbucket(unsigned int o) {
    return min((o - MN_ORD) >> BSHIFT, (unsigned)(NB2 - 1));
}

// ---------------------------------------------------------------------------
// Kernel A: streaming pass (champion structure) + fire-and-forget histogram
// update (RED to 2048 spread L2 addresses per image; no return dependency).
// ---------------------------------------------------------------------------
__global__ void __launch_bounds__(TPB) k_pass(const float* __restrict__ preds) {
    __shared__ __align__(16) ull stage[STAGE];   // 8 KB
    __shared__ int sh_cnt, sh_base, sh_ovf;

    const int b = blockIdx.y;
    const int t = threadIdx.x;
    const int lane = t & 31;

    if (t == 0) { sh_cnt = 0; sh_ovf = 0; }
    __syncthreads();

    const float4* __restrict__ sc = (const float4*)(preds + (size_t)b * 3 * HW_);
    const int tid = blockIdx.x * TPB + t;   // 0..25599

    float4 v[4];
#pragma unroll
    for (int j = 0; j < 4; j++) v[j] = sc[tid + j * 25600];

    float mx = v[0].x;
#pragma unroll
    for (int j = 0; j < 4; j++) {
        mx = fmaxf(mx, fmaxf(fmaxf(v[j].x, v[j].y), fmaxf(v[j].z, v[j].w)));
    }

    unsigned int m = 0;
    if (mx >= TG) {
#pragma unroll
        for (int j = 0; j < 4; j++) {
            m |= (v[j].x >= TG) ? (1u << (4 * j + 0)) : 0u;
            m |= (v[j].y >= TG) ? (1u << (4 * j + 1)) : 0u;
            m |= (v[j].z >= TG) ? (1u << (4 * j + 2)) : 0u;
            m |= (v[j].w >= TG) ? (1u << (4 * j + 3)) : 0u;
        }
    }

    const int nh = __popc(m);
    if (__ballot_sync(0xFFFFFFFFu, nh) != 0) {
        int pre = nh;
#pragma unroll
        for (int off = 1; off < 32; off <<= 1) {
            int y = __shfl_up_sync(0xFFFFFFFFu, pre, off);
            if (lane >= off) pre += y;
        }
        const int tot = __shfl_sync(0xFFFFFFFFu, pre, 31);
        int wbase = 0;
        if (lane == 31) wbase = atomicAdd(&sh_cnt, tot);
        wbase = __shfl_sync(0xFFFFFFFFu, wbase, 31);

        int pos = wbase + pre - nh;
        if (nh) {
#pragma unroll
            for (int j = 0; j < 4; j++) {
                const int i4 = tid + j * 25600;
                const float f0 = v[j].x, f1 = v[j].y, f2 = v[j].z, f3 = v[j].w;
#pragma unroll
                for (int k = 0; k < 4; k++) {
                    if (m & (1u << (4 * j + k))) {
                        if (pos < STAGE) {
                            const float f = (k == 0) ? f0 : (k == 1) ? f1 : (k == 2) ? f2 : f3;
                            const unsigned int o = ordf(f);
                            const unsigned int idx = (unsigned int)(i4 * 4 + k);
                            stage[pos] = ((ull)o << 32) | (ull)(0xFFFFFFFFu - idx);
                            atomicAdd(&g_hist[b * NB2 + sbucket(o)], 1u);  // RED
                        } else {
                            sh_ovf = 1;
                        }
                        pos++;
                    }
                }
            }
        }
    }
    __syncthreads();

    if (t == 0) {
        int add = sh_cnt + (sh_ovf ? 1000000 : 0);   // poison on overflow
        sh_base = add ? atomicAdd(&g_count[b], add) : 0;
    }
    __syncthreads();

    const int cnt = min(sh_cnt, STAGE);
    const int base = sh_base;
    for (int i = t; i < cnt; i += TPB) {
        const int p = base + i;
        if (p < CAP) g_cand[b * CAP + p] = stage[i];
    }
}

// ---------------------------------------------------------------------------
// Kernel B: per-image select. grid 32 x 1024.
// Histogram comes precomputed from the pass -> ONE global sweep of cand:
// load hist -> suffix scan -> scatter to shared -> parallel rank + fused emit
// -> reset g_hist / g_count.
// ---------------------------------------------------------------------------
__global__ void __launch_bounds__(1024) k_select(const float* __restrict__ preds,
                                                 float* __restrict__ out) {
    __shared__ __align__(16) ull kgrp_s[2048];       // 16 KB bucket-grouped keys
    __shared__ unsigned int hist[NB2];               //  8 KB
    __shared__ unsigned int start[NB2];              //  8 KB
    __shared__ unsigned int part[1024];              //  4 KB (fallback only)
    __shared__ unsigned int wtmp[32];
    __shared__ int sh_T, sh_c2;

    const int b = blockIdx.x;
    const int t = threadIdx.x;
    const int lane = t & 31;
    const int wid = t >> 5;

    const float* chan = preds + (size_t)b * 3 * HW_;

    int M = g_count[b];
    bool fastpath = (M >= TOPK_ && M <= CAP);

    // ============ FALLBACK (never taken for valid fast path) ============
    if (!fastpath) {
        for (int i = t; i < NB2; i += 1024) hist[i] = 0u;
        if (t == 0) { sh_T = 0; sh_c2 = 0; }
        __syncthreads();

        const float4* sc = (const float4*)chan;
        for (int i = t; i < HW_ / 4; i += 1024) {
            const float4 w = sc[i];
            atomicAdd(&hist[ordf(w.x) >> 21], 1u);
            atomicAdd(&hist[ordf(w.y) >> 21], 1u);
            atomicAdd(&hist[ordf(w.z) >> 21], 1u);
            atomicAdd(&hist[ordf(w.w) >> 21], 1u);
        }
        __syncthreads();

        const unsigned int p2 = hist[2 * t] + hist[2 * t + 1];
        part[t] = p2;
        __syncthreads();
        for (int off = 1; off < 1024; off <<= 1) {
            unsigned int vv = (t + off < 1024) ? part[t + off] : 0u;
            __syncthreads();
            part[t] += vv;
            __syncthreads();
        }
        unsigned int acc = part[t] - p2;
        for (int j = 1; j >= 0; j--) {
            acc += hist[2 * t + j];
            if (acc >= (unsigned)TOPK_) { atomicMax(&sh_T, 2 * t + j); break; }
        }
        __syncthreads();
        const unsigned int T = (unsigned int)sh_T;

        for (int i = t; i < HW_ / 4; i += 1024) {
            const float4 w = sc[i];
            const float f[4] = {w.x, w.y, w.z, w.w};
#pragma unroll
            for (int k = 0; k < 4; k++) {
                const unsigned int o = ordf(f[k]);
                if ((o >> 21) >= T) {
                    const int p = atomicAdd(&sh_c2, 1);
                    if (p < CAP) {
                        const unsigned int idx = (unsigned int)(i * 4 + k);
                        g_cand[b * CAP + p] = ((ull)o << 32) | (ull)(0xFFFFFFFFu - idx);
                    }
                }
            }
        }
        __syncthreads();
        M = min(sh_c2, CAP);
        // rebuild hist with the STATIC bucket map from the recompacted cand.
        // NOTE: fallback keys may have o < MN_ORD; sbucket clamps via unsigned
        // wrap? No — (o - MN_ORD) underflows to huge -> min() clamps to 2047
        // which is WRONG (low scores land in top bucket). Guard explicitly.
        for (int i = t; i < NB2; i += 1024) hist[i] = 0u;
        __syncthreads();
        for (int i = t; i < M; i += 1024) {
            const unsigned int o = (unsigned int)(g_cand[b * CAP + i] >> 32);
            const unsigned int bk = (o >= MN_ORD) ? sbucket(o) : 0u;
            atomicAdd(&hist[bk], 1u);
        }
        __syncthreads();
    } else {
        // load precomputed histogram (L2-hot) into shared
        for (int i = t; i < NB2; i += 1024) hist[i] = g_hist[b * NB2 + i];
        __syncthreads();
    }
    M = min(M, CAP);

    ull* kgrp = (M <= 2048) ? kgrp_s : &g_sorted[b * CAP];
    const ull* __restrict__ cand = &g_cand[b * CAP];

    // ---- hierarchical suffix scan over 2048 buckets (2 per thread) ----
    const unsigned int h0 = hist[2 * t], h1 = hist[2 * t + 1];
    const unsigned int s_own = h0 + h1;
    unsigned int s_incl = s_own;
#pragma unroll
    for (int off = 1; off < 32; off <<= 1) {
        unsigned int y = __shfl_down_sync(0xFFFFFFFFu, s_incl, off);
        if (lane + off < 32) s_incl += y;
    }
    if (lane == 0) wtmp[wid] = s_incl;
    __syncthreads();
    if (wid == 0) {
        const unsigned int wv = wtmp[lane];
        unsigned int wincl = wv;
#pragma unroll
        for (int off = 1; off < 32; off <<= 1) {
            unsigned int y = __shfl_down_sync(0xFFFFFFFFu, wincl, off);
            if (lane + off < 32) wincl += y;
        }
        wtmp[lane] = wincl - wv;   // totals of warps ABOVE this warp
    }
    __syncthreads();
    {
        const unsigned int above = wtmp[wid] + (s_incl - s_own);
        start[2 * t + 1] = above;
        start[2 * t]     = above + h1;
        hist[2 * t] = 0u; hist[2 * t + 1] = 0u;   // -> intra-bucket counters
    }
    __syncthreads();

    // ---- single global sweep: scatter to bucket-grouped shared ----
    const bool fb = !fastpath;
    for (int i = t; i < M; i += 1024) {
        const ull key = cand[i];
        const unsigned int o = (unsigned int)(key >> 32);
        const unsigned int bk = (fb && o < MN_ORD) ? 0u : sbucket(o);
        const unsigned int p = start[bk] + atomicAdd(&hist[bk], 1u);
        kgrp[p] = key;
    }
    __syncthreads();
    // hist[bk] now holds bucket count c

    // ---- parallel rank-within-bucket + fused emit ----
    const float* ph = chan + HW_;
    const float* pw = ph + HW_;
    float* boxes  = out;                              // [B, K, 4]
    float* scores = out + (size_t)B_ * TOPK_ * 4;     // [B, K]
    float* keep   = scores + (size_t)B_ * TOPK_;      // [B, K]

    for (int p = t; p < M; p += 1024) {
        const ull key = kgrp[p];
        const unsigned int o = (unsigned int)(key >> 32);
        const unsigned int bk = (fb && o < MN_ORD) ? 0u : sbucket(o);
        const unsigned int st = start[bk];
        const unsigned int c  = hist[bk];
        unsigned int r = 0;
        for (unsigned int q = 0; q < c; q++) r += (kgrp[st + q] > key);
        const unsigned int grank = st + r;   // exact global rank (keys unique)
        if (grank < (unsigned)TOPK_) {
            const unsigned int u = (o & 0x80000000u) ? (o ^ 0x80000000u) : ~o;
            const float score = __uint_as_float(u);
            const unsigned int idx = 0xFFFFFFFFu - (unsigned int)(key & 0xFFFFFFFFull);

            const float h = fmaxf(ph[idx], 1e-6f) * (float)H_;
            const float w = fmaxf(pw[idx], 1e-6f) * (float)W_;
            const float cx = (float)(idx % W_);
            const float cy = (float)(idx / W_);

            float* bx = boxes + ((size_t)b * TOPK_ + grank) * 4;
            bx[0] = cx - 0.5f * w;
            bx[1] = cy - 0.5f * h;
            bx[2] = cx + 0.5f * w;
            bx[3] = cy + 0.5f * h;
            scores[b * TOPK_ + grank] = score;
            keep[b * TOPK_ + grank]   = 1.0f;
        }
    }

    // reset state for next graph replay (g_hist written by pass every replay)
    for (int i = t; i < NB2; i += 1024) g_hist[b * NB2 + i] = 0u;
    if (t == 0) g_count[b] = 0;
}

// ---------------------------------------------------------------------------
extern "C" void kernel_launch(void* const* d_in, const int* in_sizes, int n_in,
                              void* d_out, int out_size) {
    const float* preds = (const float*)d_in[0];
    float* out = (float*)d_out;

    dim3 gp(BX, B_);
    k_pass<<<gp, TPB>>>(preds);
    k_select<<<B_, 1024>>>(preds, out);
}

// round 17
// speedup vs baseline: 1.7927x; 1.0107x over previous
#include <cuda_runtime.h>
#include <stdint.h>

// preds: [32, 3, 640, 640] fp32
#define B_     32
#define H_     640
#define W_     640
#define HW_    (H_ * W_)          // 409600 floats per channel
#define TOPK_  1000
#define NB2    2048               // sort buckets
#define CAP    4096
#define TG     2.6f               // static fast-path threshold (p~0.0047 -> ~1900/img)
#define BX     100                // pass blocks per image (4096 floats each)
#define TPB    256
#define STAGE  1024
// static monotone bucket map: ord(2.6f) = 0xC0266666, 2^13 per bucket
#define MN_ORD 0xC0266666u
#define BSHIFT 13

typedef unsigned long long ull;

// Device scratch (zero at load; k_select restores everything each execution)
__device__ ull          g_cand[B_ * CAP];
__device__ ull          g_sorted[B_ * CAP];   // used only when M > 2048
__device__ unsigned int g_hist[B_ * NB2];
__device__ int          g_count[B_];

// Order-preserving bijection float -> uint (monotone increasing)
__device__ __forceinline__ unsigned int ordf(float x) {
    unsigned int u = __float_as_uint(x);
    return (u & 0x80000000u) ? ~u : (u | 0x80000000u);
}

__device__ __forceinline__ unsigned int sbucket(unsigned int o) {
    return min((o - MN_ORD) >> BSHIFT, (unsigned)(NB2 - 1));
}

// ---------------------------------------------------------------------------
// Kernel A: streaming pass — bit-identical to R16 champion + PDL trigger.
// ---------------------------------------------------------------------------
__global__ void __launch_bounds__(TPB) k_pass(const float* __restrict__ preds) {
    __shared__ __align__(16) ull stage[STAGE];   // 8 KB
    __shared__ int sh_cnt, sh_base, sh_ovf;

    const int b = blockIdx.y;
    const int t = threadIdx.x;
    const int lane = t & 31;

    if (t == 0) { sh_cnt = 0; sh_ovf = 0; }
    __syncthreads();

    const float4* __restrict__ sc = (const float4*)(preds + (size_t)b * 3 * HW_);
    const int tid = blockIdx.x * TPB + t;   // 0..25599

    float4 v[4];
#pragma unroll
    for (int j = 0; j < 4; j++) v[j] = sc[tid + j * 25600];

    float mx = v[0].x;
#pragma unroll
    for (int j = 0; j < 4; j++) {
        mx = fmaxf(mx, fmaxf(fmaxf(v[j].x, v[j].y), fmaxf(v[j].z, v[j].w)));
    }

    unsigned int m = 0;
    if (mx >= TG) {
#pragma unroll
        for (int j = 0; j < 4; j++) {
            m |= (v[j].x >= TG) ? (1u << (4 * j + 0)) : 0u;
            m |= (v[j].y >= TG) ? (1u << (4 * j + 1)) : 0u;
            m |= (v[j].z >= TG) ? (1u << (4 * j + 2)) : 0u;
            m |= (v[j].w >= TG) ? (1u << (4 * j + 3)) : 0u;
        }
    }

    const int nh = __popc(m);
    if (__ballot_sync(0xFFFFFFFFu, nh) != 0) {
        int pre = nh;
#pragma unroll
        for (int off = 1; off < 32; off <<= 1) {
            int y = __shfl_up_sync(0xFFFFFFFFu, pre, off);
            if (lane >= off) pre += y;
        }
        const int tot = __shfl_sync(0xFFFFFFFFu, pre, 31);
        int wbase = 0;
        if (lane == 31) wbase = atomicAdd(&sh_cnt, tot);
        wbase = __shfl_sync(0xFFFFFFFFu, wbase, 31);

        int pos = wbase + pre - nh;
        if (nh) {
#pragma unroll
            for (int j = 0; j < 4; j++) {
                const int i4 = tid + j * 25600;
                const float f0 = v[j].x, f1 = v[j].y, f2 = v[j].z, f3 = v[j].w;
#pragma unroll
                for (int k = 0; k < 4; k++) {
                    if (m & (1u << (4 * j + k))) {
                        if (pos < STAGE) {
                            const float f = (k == 0) ? f0 : (k == 1) ? f1 : (k == 2) ? f2 : f3;
                            const unsigned int o = ordf(f);
                            const unsigned int idx = (unsigned int)(i4 * 4 + k);
                            stage[pos] = ((ull)o << 32) | (ull)(0xFFFFFFFFu - idx);
                            atomicAdd(&g_hist[b * NB2 + sbucket(o)], 1u);  // RED
                        } else {
                            sh_ovf = 1;
                        }
                        pos++;
                    }
                }
            }
        }
    }
    __syncthreads();

    if (t == 0) {
        int add = sh_cnt + (sh_ovf ? 1000000 : 0);   // poison on overflow
        sh_base = add ? atomicAdd(&g_count[b], add) : 0;
    }
    __syncthreads();

    const int cnt = min(sh_cnt, STAGE);
    const int base = sh_base;
    for (int i = t; i < cnt; i += TPB) {
        const int p = base + i;
        if (p < CAP) g_cand[b * CAP + p] = stage[i];
    }

    // PDL: allow the dependent k_select grid to launch early.
    cudaTriggerProgrammaticLaunchCompletion();
}

// ---------------------------------------------------------------------------
// Kernel B: per-image select — bit-identical to R16 + grid-dependency sync.
// ---------------------------------------------------------------------------
__global__ void __launch_bounds__(1024) k_select(const float* __restrict__ preds,
                                                 float* __restrict__ out) {
    __shared__ __align__(16) ull kgrp_s[2048];       // 16 KB bucket-grouped keys
    __shared__ unsigned int hist[NB2];               //  8 KB
    __shared__ unsigned int start[NB2];              //  8 KB
    __shared__ unsigned int part[1024];              //  4 KB (fallback only)
    __shared__ unsigned int wtmp[32];
    __shared__ int sh_T, sh_c2;

    const int b = blockIdx.x;
    const int t = threadIdx.x;
    const int lane = t & 31;
    const int wid = t >> 5;

    const float* chan = preds + (size_t)b * 3 * HW_;

    // Wait for all k_pass memory to be visible (PDL semantics).
    cudaGridDependencySynchronize();

    int M = g_count[b];
    bool fastpath = (M >= TOPK_ && M <= CAP);

    // ============ FALLBACK (never taken for valid fast path) ============
    if (!fastpath) {
        for (int i = t; i < NB2; i += 1024) hist[i] = 0u;
        if (t == 0) { sh_T = 0; sh_c2 = 0; }
        __syncthreads();

        const float4* sc = (const float4*)chan;
        for (int i = t; i < HW_ / 4; i += 1024) {
            const float4 w = sc[i];
            atomicAdd(&hist[ordf(w.x) >> 21], 1u);
            atomicAdd(&hist[ordf(w.y) >> 21], 1u);
            atomicAdd(&hist[ordf(w.z) >> 21], 1u);
            atomicAdd(&hist[ordf(w.w) >> 21], 1u);
        }
        __syncthreads();

        const unsigned int p2 = hist[2 * t] + hist[2 * t + 1];
        part[t] = p2;
        __syncthreads();
        for (int off = 1; off < 1024; off <<= 1) {
            unsigned int vv = (t + off < 1024) ? part[t + off] : 0u;
            __syncthreads();
            part[t] += vv;
            __syncthreads();
        }
        unsigned int acc = part[t] - p2;
        for (int j = 1; j >= 0; j--) {
            acc += hist[2 * t + j];
            if (acc >= (unsigned)TOPK_) { atomicMax(&sh_T, 2 * t + j); break; }
        }
        __syncthreads();
        const unsigned int T = (unsigned int)sh_T;

        for (int i = t; i < HW_ / 4; i += 1024) {
            const float4 w = sc[i];
            const float f[4] = {w.x, w.y, w.z, w.w};
#pragma unroll
            for (int k = 0; k < 4; k++) {
                const unsigned int o = ordf(f[k]);
                if ((o >> 21) >= T) {
                    const int p = atomicAdd(&sh_c2, 1);
                    if (p < CAP) {
                        const unsigned int idx = (unsigned int)(i * 4 + k);
                        g_cand[b * CAP + p] = ((ull)o << 32) | (ull)(0xFFFFFFFFu - idx);
                    }
                }
            }
        }
        __syncthreads();
        M = min(sh_c2, CAP);
        // rebuild hist with the STATIC bucket map (guard o < MN_ORD -> bucket 0)
        for (int i = t; i < NB2; i += 1024) hist[i] = 0u;
        __syncthreads();
        for (int i = t; i < M; i += 1024) {
            const unsigned int o = (unsigned int)(g_cand[b * CAP + i] >> 32);
            const unsigned int bk = (o >= MN_ORD) ? sbucket(o) : 0u;
            atomicAdd(&hist[bk], 1u);
        }
        __syncthreads();
    } else {
        // load precomputed histogram (L2-hot) into shared
        for (int i = t; i < NB2; i += 1024) hist[i] = g_hist[b * NB2 + i];
        __syncthreads();
    }
    M = min(M, CAP);

    ull* kgrp = (M <= 2048) ? kgrp_s : &g_sorted[b * CAP];
    const ull* __restrict__ cand = &g_cand[b * CAP];

    // ---- hierarchical suffix scan over 2048 buckets (2 per thread) ----
    const unsigned int h0 = hist[2 * t], h1 = hist[2 * t + 1];
    const unsigned int s_own = h0 + h1;
    unsigned int s_incl = s_own;
#pragma unroll
    for (int off = 1; off < 32; off <<= 1) {
        unsigned int y = __shfl_down_sync(0xFFFFFFFFu, s_incl, off);
        if (lane + off < 32) s_incl += y;
    }
    if (lane == 0) wtmp[wid] = s_incl;
    __syncthreads();
    if (wid == 0) {
        const unsigned int wv = wtmp[lane];
        unsigned int wincl = wv;
#pragma unroll
        for (int off = 1; off < 32; off <<= 1) {
            unsigned int y = __shfl_down_sync(0xFFFFFFFFu, wincl, off);
            if (lane + off < 32) wincl += y;
        }
        wtmp[lane] = wincl - wv;   // totals of warps ABOVE this warp
    }
    __syncthreads();
    {
        const unsigned int above = wtmp[wid] + (s_incl - s_own);
        start[2 * t + 1] = above;
        start[2 * t]     = above + h1;
        hist[2 * t] = 0u; hist[2 * t + 1] = 0u;   // -> intra-bucket counters
    }
    __syncthreads();

    // ---- single global sweep: scatter to bucket-grouped shared ----
    const bool fb = !fastpath;
    for (int i = t; i < M; i += 1024) {
        const ull key = cand[i];
        const unsigned int o = (unsigned int)(key >> 32);
        const unsigned int bk = (fb && o < MN_ORD) ? 0u : sbucket(o);
        const unsigned int p = start[bk] + atomicAdd(&hist[bk], 1u);
        kgrp[p] = key;
    }
    __syncthreads();
    // hist[bk] now holds bucket count c

    // ---- parallel rank-within-bucket + fused emit ----
    const float* ph = chan + HW_;
    const float* pw = ph + HW_;
    float* boxes  = out;                              // [B, K, 4]
    float* scores = out + (size_t)B_ * TOPK_ * 4;     // [B, K]
    float* keep   = scores + (size_t)B_ * TOPK_;      // [B, K]

    for (int p = t; p < M; p += 1024) {
        const ull key = kgrp[p];
        const unsigned int o = (unsigned int)(key >> 32);
        const unsigned int bk = (fb && o < MN_ORD) ? 0u : sbucket(o);
        const unsigned int st = start[bk];
        const unsigned int c  = hist[bk];
        unsigned int r = 0;
        for (unsigned int q = 0; q < c; q++) r += (kgrp[st + q] > key);
        const unsigned int grank = st + r;   // exact global rank (keys unique)
        if (grank < (unsigned)TOPK_) {
            const unsigned int u = (o & 0x80000000u) ? (o ^ 0x80000000u) : ~o;
            const float score = __uint_as_float(u);
            const unsigned int idx = 0xFFFFFFFFu - (unsigned int)(key & 0xFFFFFFFFull);

            const float h = fmaxf(ph[idx], 1e-6f) * (float)H_;
            const float w = fmaxf(pw[idx], 1e-6f) * (float)W_;
            const float cx = (float)(idx % W_);
            const float cy = (float)(idx / W_);

            float* bx = boxes + ((size_t)b * TOPK_ + grank) * 4;
            bx[0] = cx - 0.5f * w;
            bx[1] = cy - 0.5f * h;
            bx[2] = cx + 0.5f * w;
            bx[3] = cy + 0.5f * h;
            scores[b * TOPK_ + grank] = score;
            keep[b * TOPK_ + grank]   = 1.0f;
        }
    }

    // reset state for next graph replay (g_hist rewritten by pass every replay)
    for (int i = t; i < NB2; i += 1024) g_hist[b * NB2 + i] = 0u;
    if (t == 0) g_count[b] = 0;
}

// ---------------------------------------------------------------------------
extern "C" void kernel_launch(void* const* d_in, const int* in_sizes, int n_in,
                              void* d_out, int out_size) {
    const float* preds = (const float*)d_in[0];
    float* out = (float*)d_out;

    dim3 gp(BX, B_);
    k_pass<<<gp, TPB>>>(preds);

    // k_select with programmatic dependent launch: launches/ramps while
    // k_pass is still running; data safety via cudaGridDependencySynchronize.
    cudaLaunchConfig_t cfg = {};
    cfg.gridDim = dim3(B_, 1, 1);
    cfg.blockDim = dim3(1024, 1, 1);
    cudaLaunchAttribute attrs[1];
    attrs[0].id = cudaLaunchAttributeProgrammaticStreamSerialization;
    attrs[0].val.programmaticStreamSerializationAllowed = 1;
    cfg.attrs = attrs;
    cfg.numAttrs = 1;
    cudaLaunchKernelEx(&cfg, k_select, preds, out);
}